// round 5
// baseline (speedup 1.0000x reference)
#include <cuda_runtime.h>

#define N_TOK 16384      // B*S = 4*4096
#define DDIM  2048
#define NEXP  64
#define TOPK  8
#define BM    128        // tokens per block
#define BK    16         // k-tile
#define NT    (DDIM/BK)  // 128 k-tiles
#define AS_STRIDE 132    // padded to keep STS conflict-free and 8B-aligned rows

__device__ __forceinline__ unsigned long long pack2(float lo, float hi) {
    unsigned long long r;
    asm("mov.b64 %0, {%1,%2};" : "=l"(r) : "f"(lo), "f"(hi));
    return r;
}
__device__ __forceinline__ void unpack2(unsigned long long v, float& lo, float& hi) {
    asm("mov.b64 {%0,%1}, %2;" : "=f"(lo), "=f"(hi) : "l"(v));
}
__device__ __forceinline__ unsigned long long fma2(unsigned long long a,
                                                   unsigned long long b,
                                                   unsigned long long c) {
    unsigned long long d;
    asm("fma.rn.f32x2 %0, %1, %2, %3;" : "=l"(d) : "l"(a), "l"(b), "l"(c));
    return d;
}
__device__ __forceinline__ unsigned long long mul2(unsigned long long a,
                                                   unsigned long long b) {
    unsigned long long d;
    asm("mul.rn.f32x2 %0, %1, %2;" : "=l"(d) : "l"(a), "l"(b));
    return d;
}
__device__ __forceinline__ unsigned long long add2(unsigned long long a,
                                                   unsigned long long b) {
    unsigned long long d;
    asm("add.rn.f32x2 %0, %1, %2;" : "=l"(d) : "l"(a), "l"(b));
    return d;
}

__global__ __launch_bounds__(256, 1)
void noisyk_gate_kernel(const float* __restrict__ x,
                        const float* __restrict__ W,
                        const float* __restrict__ bias,
                        float* __restrict__ g_out,
                        float* __restrict__ idx_out,
                        float* __restrict__ sc_out)
{
    __shared__ union {
        struct {
            float As[2][BK][AS_STRIDE];  // transposed x tile: [k][token]
            float Bs[2][BK][NEXP];       // W tile: [k][expert]
        } t;
        float Ss[BM][NEXP + 1];          // post-sigmoid scores for top-k
    } sm;

    const int tid = threadIdx.x;
    const int tx  = tid & 7;    // expert group: experts tx*8 .. tx*8+7
    const int ty  = tid >> 3;   // token group:  tokens ty*4 .. ty*4+3
    const int tokRow = blockIdx.x * BM;

    // ---- global load mappings ----
    const int am = tid >> 1;
    const int ah = (tid & 1) * 8;
    const float* xrow = x + (size_t)(tokRow + am) * DDIM + ah;
    const int bk = tid >> 4;          // 0..15
    const int be = (tid & 15) * 4;    // 0..60

    // ---- prefetch tile 0 ----
    float4 pa0 = *(const float4*)(xrow + 0);
    float4 pa1 = *(const float4*)(xrow + 4);
    float4 pb  = *(const float4*)(W + (size_t)bk * NEXP + be);
    {
        float av[8] = {pa0.x, pa0.y, pa0.z, pa0.w, pa1.x, pa1.y, pa1.z, pa1.w};
        #pragma unroll
        for (int c = 0; c < 8; c++) sm.t.As[0][ah + c][am] = av[c];
        *(float4*)&sm.t.Bs[0][bk][be] = pb;
    }

    // Hierarchical accumulators (error control vs reference ordering):
    //   acc_t : one BK=16 tile   (error ~2e-8)
    //   acc_s : 16 tiles = 256 k (error ~1e-7)
    //   acc_g : grand total of 8 superchunks (error ~1.5e-7)
    unsigned long long acc_t[4][4];
    unsigned long long acc_s[4][4];
    unsigned long long acc_g[4][4];

    float bj[8];
    #pragma unroll
    for (int j = 0; j < 8; j++) bj[j] = bias[tx * 8 + j];

    __syncthreads();

    int buf = 0;
    for (int kt = 0; kt < NT; ++kt) {
        // prefetch next tile into registers
        if (kt + 1 < NT) {
            const float* xn = xrow + (size_t)(kt + 1) * BK;
            pa0 = *(const float4*)(xn);
            pa1 = *(const float4*)(xn + 4);
            pb  = *(const float4*)(W + (size_t)((kt + 1) * BK + bk) * NEXP + be);
        }

        // ---- compute current tile into fresh acc_t ----
        // kk = 0: multiply (initializes acc_t, no zero-fill needed)
        {
            float2 a0 = *(const float2*)&sm.t.As[buf][0][ty * 4];
            float2 a1 = *(const float2*)&sm.t.As[buf][0][ty * 4 + 2];
            unsigned long long bb[4];
            #pragma unroll
            for (int jp = 0; jp < 4; jp++)
                bb[jp] = *(const unsigned long long*)&sm.t.Bs[buf][0][tx * 8 + jp * 2];
            unsigned long long aa[4];
            aa[0] = pack2(a0.x, a0.x);
            aa[1] = pack2(a0.y, a0.y);
            aa[2] = pack2(a1.x, a1.x);
            aa[3] = pack2(a1.y, a1.y);
            #pragma unroll
            for (int i = 0; i < 4; i++)
                #pragma unroll
                for (int jp = 0; jp < 4; jp++)
                    acc_t[i][jp] = mul2(aa[i], bb[jp]);
        }
        #pragma unroll
        for (int kk = 1; kk < BK; ++kk) {
            float2 a0 = *(const float2*)&sm.t.As[buf][kk][ty * 4];
            float2 a1 = *(const float2*)&sm.t.As[buf][kk][ty * 4 + 2];
            unsigned long long bb[4];
            #pragma unroll
            for (int jp = 0; jp < 4; jp++)
                bb[jp] = *(const unsigned long long*)&sm.t.Bs[buf][kk][tx * 8 + jp * 2];
            unsigned long long aa[4];
            aa[0] = pack2(a0.x, a0.x);
            aa[1] = pack2(a0.y, a0.y);
            aa[2] = pack2(a1.x, a1.x);
            aa[3] = pack2(a1.y, a1.y);
            #pragma unroll
            for (int i = 0; i < 4; i++)
                #pragma unroll
                for (int jp = 0; jp < 4; jp++)
                    acc_t[i][jp] = fma2(aa[i], bb[jp], acc_t[i][jp]);
        }

        // ---- hierarchical merge: tile -> super -> grand ----
        const int m = kt & 15;
        if (m == 0) {
            #pragma unroll
            for (int i = 0; i < 4; i++)
                #pragma unroll
                for (int jp = 0; jp < 4; jp++) acc_s[i][jp] = acc_t[i][jp];
        } else {
            #pragma unroll
            for (int i = 0; i < 4; i++)
                #pragma unroll
                for (int jp = 0; jp < 4; jp++) acc_s[i][jp] = add2(acc_s[i][jp], acc_t[i][jp]);
        }
        if (m == 15) {
            if (kt == 15) {
                #pragma unroll
                for (int i = 0; i < 4; i++)
                    #pragma unroll
                    for (int jp = 0; jp < 4; jp++) acc_g[i][jp] = acc_s[i][jp];
            } else {
                #pragma unroll
                for (int i = 0; i < 4; i++)
                    #pragma unroll
                    for (int jp = 0; jp < 4; jp++) acc_g[i][jp] = add2(acc_g[i][jp], acc_s[i][jp]);
            }
        }

        // stage next tile into the other smem buffer
        if (kt + 1 < NT) {
            const int nb = buf ^ 1;
            float av[8] = {pa0.x, pa0.y, pa0.z, pa0.w, pa1.x, pa1.y, pa1.z, pa1.w};
            #pragma unroll
            for (int c = 0; c < 8; c++) sm.t.As[nb][ah + c][am] = av[c];
            *(float4*)&sm.t.Bs[nb][bk][be] = pb;
        }
        __syncthreads();
        buf ^= 1;
    }

    // ---- epilogue: bias + sigmoid (precise expf), write scores ----
    #pragma unroll
    for (int i = 0; i < 4; i++) {
        const int tl = ty * 4 + i;
        float v[8];
        #pragma unroll
        for (int jp = 0; jp < 4; jp++) unpack2(acc_g[i][jp], v[2 * jp], v[2 * jp + 1]);
        float s[8];
        #pragma unroll
        for (int j = 0; j < 8; j++) {
            float z = v[j] + bj[j];
            // numerically-stable logistic matching jax.nn.sigmoid
            if (z >= 0.0f) {
                s[j] = 1.0f / (1.0f + expf(-z));
            } else {
                float e = expf(z);
                s[j] = e / (1.0f + e);
            }
        }
        #pragma unroll
        for (int j = 0; j < 8; j++) sm.Ss[tl][tx * 8 + j] = s[j];
        float4* sc = (float4*)(sc_out + (size_t)(tokRow + tl) * NEXP + tx * 8);
        sc[0] = make_float4(s[0], s[1], s[2], s[3]);
        sc[1] = make_float4(s[4], s[5], s[6], s[7]);
    }
    __syncthreads();

    // ---- top-8 per token: serial insertion, strict '>' => lowest-index-first
    //      on ties, identical to jax.lax.top_k ----
    if (tid < BM) {
        float vals[TOPK];
        int   ids[TOPK];
        #pragma unroll
        for (int j = 0; j < TOPK; j++) { vals[j] = -1e30f; ids[j] = 0; }
        for (int e = 0; e < NEXP; e++) {
            float sv = sm.Ss[tid][e];
            if (sv > vals[TOPK - 1]) {
                int p = TOPK - 1;
                while (p > 0 && sv > vals[p - 1]) {
                    vals[p] = vals[p - 1];
                    ids[p]  = ids[p - 1];
                    p--;
                }
                vals[p] = sv;
                ids[p]  = e;
            }
        }
        float sum = 0.0f;
        #pragma unroll
        for (int j = 0; j < TOPK; j++) sum += vals[j];
        const float inv = 1.0f / sum;
        const size_t base = (size_t)(tokRow + tid) * TOPK;
        #pragma unroll
        for (int j = 0; j < TOPK; j++) {
            g_out[base + j]   = vals[j] * inv;
            idx_out[base + j] = (float)ids[j];
        }
    }
}

extern "C" void kernel_launch(void* const* d_in, const int* in_sizes, int n_in,
                              void* d_out, int out_size)
{
    const float* x = (const float*)d_in[0];
    const float* W = (const float*)d_in[1];
    const float* b = (const float*)d_in[2];
    // d_in[3] is k (always 8 here)

    float* out     = (float*)d_out;
    float* g_out   = out;                                  // [16384, 8]
    float* idx_out = out + (size_t)N_TOK * TOPK;           // [16384, 8] (as float)
    float* sc_out  = out + (size_t)2 * N_TOK * TOPK;       // [16384, 64]

    noisyk_gate_kernel<<<N_TOK / BM, 256>>>(x, W, b, g_out, idx_out, sc_out);
}